// round 1
// baseline (speedup 1.0000x reference)
#include <cuda_runtime.h>
#include <stdint.h>

// Problem constants
#define NN 50000
#define EE 600000
#define FF 128
#define HH 128
#define OO 64
#define RR 8
#define KT (RR * FF)   // 1024 = flattened (relation, feature) K dim
#define KTOT (KT + FF) // 1152 = + root-transform K

// ---------------------------------------------------------------------------
// Device scratch (allocation-free rule: __device__ globals)
// ---------------------------------------------------------------------------
__device__ float    g_T[(size_t)NN * KT];   // 204.8 MB scatter accumulator
__device__ float    g_h[(size_t)NN * HH];   // 25.6 MB layer-1 output
__device__ int      g_cnt[NN];
__device__ float    g_inv[NN];
__device__ unsigned g_mm[2];                // min/max bits of edge_weight
__device__ int      g_is64;                 // 1 if indices are int64

// ---------------------------------------------------------------------------
// Helpers
// ---------------------------------------------------------------------------
__device__ __forceinline__ int load_idx(const void* p, size_t i) {
    return g_is64 ? (int)((const long long*)p)[i] : ((const int*)p)[i];
}

// Detect index dtype: for int64 (values in [0, 2^31)), every odd 32-bit word
// is a zero high word. For int32, odd words are real indices (~N/2 mean) —
// probability all 1000 sampled are zero is negligible.
__global__ void k_detect(const void* ei) {
    const int* p = (const int*)ei;
    int nz = 0;
    for (int i = 1; i < 2001; i += 2) nz |= p[i];
    g_is64 = (nz == 0) ? 1 : 0;
}

__global__ void k_zero_cnt() {
    int i = blockIdx.x * blockDim.x + threadIdx.x;
    if (i < NN) g_cnt[i] = 0;
    if (i == 0) { g_mm[0] = 0xFFFFFFFFu; g_mm[1] = 0u; }
}

// One pass over edges: min/max of edge_weight (positive floats -> uint bit
// ordering is monotonic) + in-degree counts.
__global__ void k_edge_stats(const void* __restrict__ ei,
                             const float* __restrict__ ew) {
    __shared__ unsigned smn, smx;
    if (threadIdx.x == 0) { smn = 0xFFFFFFFFu; smx = 0u; }
    __syncthreads();
    unsigned mn = 0xFFFFFFFFu, mx = 0u;
    for (int e = blockIdx.x * blockDim.x + threadIdx.x; e < EE;
         e += gridDim.x * blockDim.x) {
        unsigned b = __float_as_uint(ew[e]);
        mn = min(mn, b); mx = max(mx, b);
        int dst = load_idx(ei, (size_t)EE + e);
        atomicAdd(&g_cnt[dst], 1);
    }
    #pragma unroll
    for (int o = 16; o; o >>= 1) {
        mn = min(mn, __shfl_xor_sync(0xFFFFFFFFu, mn, o));
        mx = max(mx, __shfl_xor_sync(0xFFFFFFFFu, mx, o));
    }
    if ((threadIdx.x & 31) == 0) { atomicMin(&smn, mn); atomicMax(&smx, mx); }
    __syncthreads();
    if (threadIdx.x == 0) { atomicMin(&g_mm[0], smn); atomicMax(&g_mm[1], smx); }
}

__global__ void k_inv() {
    int i = blockIdx.x * blockDim.x + threadIdx.x;
    if (i < NN) g_inv[i] = 1.0f / (float)max(g_cnt[i], 1);
}

__global__ void k_zeroT() {
    const size_t total = (size_t)NN * KT / 4;
    float4 z = make_float4(0.f, 0.f, 0.f, 0.f);
    float4* p = (float4*)g_T;
    for (size_t i = blockIdx.x * blockDim.x + threadIdx.x; i < total;
         i += (size_t)gridDim.x * blockDim.x)
        p[i] = z;
}

// Scatter: one warp per edge. T[dst, et, :] += wn * inv_cnt[dst] * X[src, :]
// Lane f-stride 32 -> each red.add instruction covers a contiguous 128B line.
__global__ void k_scatter(const float* __restrict__ X,
                          const void* __restrict__ ei,
                          const float* __restrict__ ew,
                          const void* __restrict__ et) {
    int e = (blockIdx.x * blockDim.x + threadIdx.x) >> 5;
    int lane = threadIdx.x & 31;
    if (e >= EE) return;
    int src = load_idx(ei, e);
    int dst = load_idx(ei, (size_t)EE + e);
    int r   = load_idx(et, e);
    float mn = __uint_as_float(g_mm[0]);
    float mx = __uint_as_float(g_mm[1]);
    float coef = (ew[e] - mn) / (mx - mn + 1e-8f) * g_inv[dst];
    const float* xr = X + (size_t)src * FF;
    float* tr = g_T + ((size_t)dst * RR + r) * FF;
    #pragma unroll
    for (int q = 0; q < 4; q++) {
        int f = lane + q * 32;
        atomicAdd(tr + f, coef * __ldg(xr + f));
    }
}

// ---------------------------------------------------------------------------
// Fused GEMM: out[n,h] = sum_{k<1024} T[n,k]*W[k,h] + sum_{f} X[n,f]*Rt[f,h]
//                        + bias[h]   (optional ReLU)
// A = [T | X] concatenated along K (KTOT=1152, BK=8 divides both regions).
// Classic 128xBN blocktile, 256 threads, 8xTN thread tile, fp32 FFMA.
// ---------------------------------------------------------------------------
template <int BN, int TN, bool RELU>
__global__ void __launch_bounds__(256, 2)
k_gemm(const float* __restrict__ A0,   // [N, 1024]
       const float* __restrict__ W,    // [1024, BN]
       const float* __restrict__ X,    // [N, 128]
       const float* __restrict__ Rt,   // [128, BN]
       const float* __restrict__ bias, // [BN]
       float* __restrict__ out) {      // [N, BN]
    const int BM = 128, BK = 8;
    __shared__ float As[BK][BM];
    __shared__ float Bs[BK][BN];
    int tid = threadIdx.x;
    int tx = tid & 15, ty = tid >> 4;
    int row0 = blockIdx.x * BM;

    float acc[8][TN];
    #pragma unroll
    for (int i = 0; i < 8; i++)
        #pragma unroll
        for (int j = 0; j < TN; j++) acc[i][j] = 0.f;

    int arow = tid >> 1, acol = (tid & 1) * 4;
    int n_a = row0 + arow;
    bool avalid = (n_a < NN);

    for (int k0 = 0; k0 < KTOT; k0 += BK) {
        // ---- A tile (128 x 8): one float4 per thread ----
        int ka = k0 + acol;
        float4 av = make_float4(0.f, 0.f, 0.f, 0.f);
        if (avalid) {
            const float* ap = (ka < KT)
                ? (A0 + (size_t)n_a * KT + ka)
                : (X + (size_t)n_a * FF + (ka - KT));
            av = *(const float4*)ap;
        }
        As[acol + 0][arow] = av.x; As[acol + 1][arow] = av.y;
        As[acol + 2][arow] = av.z; As[acol + 3][arow] = av.w;
        // ---- B tile (8 x BN) ----
        if (BN == 128) {
            int brow = tid >> 5, bcol = (tid & 31) * 4;
            int kb = k0 + brow;
            const float* bp = (kb < KT) ? (W + (size_t)kb * BN + bcol)
                                        : (Rt + (size_t)(kb - KT) * BN + bcol);
            *(float4*)&Bs[brow][bcol] = *(const float4*)bp;
        } else {  // BN == 64
            int brow = tid >> 5, bcol = (tid & 31) * 2;
            int kb = k0 + brow;
            const float* bp = (kb < KT) ? (W + (size_t)kb * BN + bcol)
                                        : (Rt + (size_t)(kb - KT) * BN + bcol);
            *(float2*)&Bs[brow][bcol] = *(const float2*)bp;
        }
        __syncthreads();

        #pragma unroll
        for (int kk = 0; kk < BK; kk++) {
            float4 a0 = *(float4*)&As[kk][ty * 8];
            float4 a1 = *(float4*)&As[kk][ty * 8 + 4];
            float ar[8] = {a0.x, a0.y, a0.z, a0.w, a1.x, a1.y, a1.z, a1.w};
            float br[TN];
            #pragma unroll
            for (int j = 0; j < TN; j += 4) {
                float4 b = *(float4*)&Bs[kk][tx * TN + j];
                br[j] = b.x; br[j + 1] = b.y; br[j + 2] = b.z; br[j + 3] = b.w;
            }
            #pragma unroll
            for (int i = 0; i < 8; i++)
                #pragma unroll
                for (int j = 0; j < TN; j++)
                    acc[i][j] += ar[i] * br[j];
        }
        __syncthreads();
    }

    #pragma unroll
    for (int i = 0; i < 8; i++) {
        int n = row0 + ty * 8 + i;
        if (n >= NN) continue;
        #pragma unroll
        for (int j = 0; j < TN; j++) {
            int h = tx * TN + j;
            float v = acc[i][j] + bias[h];
            if (RELU) v = fmaxf(v, 0.f);
            out[(size_t)n * BN + h] = v;
        }
    }
}

// ---------------------------------------------------------------------------
// Launch
// ---------------------------------------------------------------------------
extern "C" void kernel_launch(void* const* d_in, const int* in_sizes, int n_in,
                              void* d_out, int out_size) {
    const float* x     = (const float*)d_in[0];
    const void*  ei    = d_in[1];
    const float* ew    = (const float*)d_in[2];
    const void*  et    = d_in[3];
    const float* W1    = (const float*)d_in[4];
    const float* root1 = (const float*)d_in[5];
    const float* bias1 = (const float*)d_in[6];
    const float* W2    = (const float*)d_in[7];
    const float* root2 = (const float*)d_in[8];
    const float* bias2 = (const float*)d_in[9];
    float* out = (float*)d_out;

    void *pT = nullptr, *ph = nullptr;
    cudaGetSymbolAddress(&pT, g_T);
    cudaGetSymbolAddress(&ph, g_h);
    const float* Tp = (const float*)pT;
    float*       hp = (float*)ph;

    k_detect<<<1, 1>>>(ei);
    k_zero_cnt<<<(NN + 255) / 256, 256>>>();
    k_edge_stats<<<1024, 256>>>(ei, ew);
    k_inv<<<(NN + 255) / 256, 256>>>();

    // ---- layer 1 ----
    k_zeroT<<<2048, 256>>>();
    k_scatter<<<(EE * 32 + 255) / 256, 256>>>(x, ei, ew, et);
    k_gemm<128, 8, true><<<(NN + 127) / 128, 256>>>(Tp, W1, x, root1, bias1, hp);

    // ---- layer 2 ----
    k_zeroT<<<2048, 256>>>();
    k_scatter<<<(EE * 32 + 255) / 256, 256>>>(hp, ei, ew, et);
    k_gemm<64, 4, false><<<(NN + 127) / 128, 256>>>(Tp, W2, hp, root2, bias2, out);
}

// round 2
// speedup vs baseline: 1.0710x; 1.0710x over previous
#include <cuda_runtime.h>
#include <stdint.h>

// Problem constants
#define NN 50000
#define EE 600000
#define FF 128
#define HH 128
#define OO 64
#define RR 8
#define KT (RR * FF)   // 1024 = flattened (relation, feature) K dim
#define KTOT (KT + FF) // 1152 = + root-transform K

// ---------------------------------------------------------------------------
// Device scratch (allocation-free rule: __device__ globals)
// ---------------------------------------------------------------------------
__device__ float    g_T[(size_t)NN * KT];   // 204.8 MB scatter accumulator
__device__ float    g_h[(size_t)NN * HH];   // 25.6 MB layer-1 output
__device__ int      g_cnt[NN];
__device__ float    g_inv[NN];
__device__ unsigned g_mm[2];                // min/max bits of edge_weight
__device__ int      g_is64;                 // 1 if indices are int64

// ---------------------------------------------------------------------------
// Helpers
// ---------------------------------------------------------------------------
__device__ __forceinline__ int load_idx(const void* p, size_t i) {
    return g_is64 ? (int)((const long long*)p)[i] : ((const int*)p)[i];
}

// Packed fp32x2 FMA (sm_100+): d = a*b + d elementwise on a 64-bit pair.
__device__ __forceinline__ void fma2(unsigned long long& d,
                                     unsigned long long a,
                                     unsigned long long b) {
    asm("fma.rn.f32x2 %0, %1, %2, %0;" : "+l"(d) : "l"(a), "l"(b));
}
__device__ __forceinline__ unsigned long long swap64(unsigned long long v) {
    return (v >> 32) | (v << 32);
}
__device__ __forceinline__ float lo32(unsigned long long v) {
    return __uint_as_float((unsigned)v);
}
__device__ __forceinline__ float hi32(unsigned long long v) {
    return __uint_as_float((unsigned)(v >> 32));
}

// Detect index dtype: int64 values < 2^31 have zero odd 32-bit words.
__global__ void k_detect(const void* ei) {
    const int* p = (const int*)ei;
    int nz = 0;
    for (int i = 1; i < 2001; i += 2) nz |= p[i];
    g_is64 = (nz == 0) ? 1 : 0;
}

__global__ void k_zero_cnt() {
    int i = blockIdx.x * blockDim.x + threadIdx.x;
    if (i < NN) g_cnt[i] = 0;
    if (i == 0) { g_mm[0] = 0xFFFFFFFFu; g_mm[1] = 0u; }
}

// One pass over edges: min/max of edge_weight + in-degree counts.
__global__ void k_edge_stats(const void* __restrict__ ei,
                             const float* __restrict__ ew) {
    __shared__ unsigned smn, smx;
    if (threadIdx.x == 0) { smn = 0xFFFFFFFFu; smx = 0u; }
    __syncthreads();
    unsigned mn = 0xFFFFFFFFu, mx = 0u;
    for (int e = blockIdx.x * blockDim.x + threadIdx.x; e < EE;
         e += gridDim.x * blockDim.x) {
        unsigned b = __float_as_uint(ew[e]);
        mn = min(mn, b); mx = max(mx, b);
        int dst = load_idx(ei, (size_t)EE + e);
        atomicAdd(&g_cnt[dst], 1);
    }
    #pragma unroll
    for (int o = 16; o; o >>= 1) {
        mn = min(mn, __shfl_xor_sync(0xFFFFFFFFu, mn, o));
        mx = max(mx, __shfl_xor_sync(0xFFFFFFFFu, mx, o));
    }
    if ((threadIdx.x & 31) == 0) { atomicMin(&smn, mn); atomicMax(&smx, mx); }
    __syncthreads();
    if (threadIdx.x == 0) { atomicMin(&g_mm[0], smn); atomicMax(&g_mm[1], smx); }
}

__global__ void k_inv() {
    int i = blockIdx.x * blockDim.x + threadIdx.x;
    if (i < NN) g_inv[i] = 1.0f / (float)max(g_cnt[i], 1);
}

__global__ void k_zeroT() {
    const size_t total = (size_t)NN * KT / 4;
    float4 z = make_float4(0.f, 0.f, 0.f, 0.f);
    float4* p = (float4*)g_T;
    for (size_t i = blockIdx.x * blockDim.x + threadIdx.x; i < total;
         i += (size_t)gridDim.x * blockDim.x)
        p[i] = z;
}

// Scatter: one warp per edge. T[dst, et, :] += wn * inv_cnt[dst] * X[src, :]
__global__ void k_scatter(const float* __restrict__ X,
                          const void* __restrict__ ei,
                          const float* __restrict__ ew,
                          const void* __restrict__ et) {
    int e = (blockIdx.x * blockDim.x + threadIdx.x) >> 5;
    int lane = threadIdx.x & 31;
    if (e >= EE) return;
    int src = load_idx(ei, e);
    int dst = load_idx(ei, (size_t)EE + e);
    int r   = load_idx(et, e);
    float mn = __uint_as_float(g_mm[0]);
    float mx = __uint_as_float(g_mm[1]);
    float coef = (ew[e] - mn) / (mx - mn + 1e-8f) * g_inv[dst];
    const float* xr = X + (size_t)src * FF;
    float* tr = g_T + ((size_t)dst * RR + r) * FF;
    #pragma unroll
    for (int q = 0; q < 4; q++) {
        int f = lane + q * 32;
        atomicAdd(tr + f, coef * __ldg(xr + f));
    }
}

// ---------------------------------------------------------------------------
// Fused GEMM with packed fp32x2 FMA:
// out[n,h] = sum_{k<1024} T[n,k]*W[k,h] + sum_f X[n,f]*Rt[f,h] + bias[h]
// A = [T | X] along K (KTOT=1152). 128xBN blocktile, 256 threads, 8xTN tile.
// Pair-wise outer product: natural a/b pairs from LDS.128; cross terms via one
// swapped b pair per jp. Epilogue unscrambles the checkerboard.
// ---------------------------------------------------------------------------
template <int BN, int TN, bool RELU>
__global__ void __launch_bounds__(256, 2)
k_gemm(const float* __restrict__ A0,   // [N, 1024]
       const float* __restrict__ W,    // [1024, BN]
       const float* __restrict__ X,    // [N, 128]
       const float* __restrict__ Rt,   // [128, BN]
       const float* __restrict__ bias, // [BN]
       float* __restrict__ out) {      // [N, BN]
    const int BM = 128, BK = 8;
    const int JP = TN / 2;
    __shared__ __align__(16) float As[BK][BM];
    __shared__ __align__(16) float Bs[BK][BN];
    int tid = threadIdx.x;
    int tx = tid & 15, ty = tid >> 4;
    int row0 = blockIdx.x * BM;

    // accN[ip][jp] = (a_{2ip}b_{2jp}, a_{2ip+1}b_{2jp+1})
    // accX[ip][jp] = (a_{2ip}b_{2jp+1}, a_{2ip+1}b_{2jp})
    unsigned long long accN[4][JP], accX[4][JP];
    #pragma unroll
    for (int i = 0; i < 4; i++)
        #pragma unroll
        for (int j = 0; j < JP; j++) { accN[i][j] = 0ull; accX[i][j] = 0ull; }

    int arow = tid >> 1, acol = (tid & 1) * 4;
    int n_a = row0 + arow;
    bool avalid = (n_a < NN);

    for (int k0 = 0; k0 < KTOT; k0 += BK) {
        // ---- A tile (128 x 8): one float4 per thread ----
        int ka = k0 + acol;
        float4 av = make_float4(0.f, 0.f, 0.f, 0.f);
        if (avalid) {
            const float* ap = (ka < KT)
                ? (A0 + (size_t)n_a * KT + ka)
                : (X + (size_t)n_a * FF + (ka - KT));
            av = *(const float4*)ap;
        }
        As[acol + 0][arow] = av.x; As[acol + 1][arow] = av.y;
        As[acol + 2][arow] = av.z; As[acol + 3][arow] = av.w;
        // ---- B tile (8 x BN) ----
        if (BN == 128) {
            int brow = tid >> 5, bcol = (tid & 31) * 4;
            int kb = k0 + brow;
            const float* bp = (kb < KT) ? (W + (size_t)kb * BN + bcol)
                                        : (Rt + (size_t)(kb - KT) * BN + bcol);
            *(float4*)&Bs[brow][bcol] = *(const float4*)bp;
        } else {  // BN == 64
            int brow = tid >> 5, bcol = (tid & 31) * 2;
            int kb = k0 + brow;
            const float* bp = (kb < KT) ? (W + (size_t)kb * BN + bcol)
                                        : (Rt + (size_t)(kb - KT) * BN + bcol);
            *(float2*)&Bs[brow][bcol] = *(const float2*)bp;
        }
        __syncthreads();

        #pragma unroll
        for (int kk = 0; kk < BK; kk++) {
            ulonglong2 a01 = *(ulonglong2*)&As[kk][ty * 8];
            ulonglong2 a23 = *(ulonglong2*)&As[kk][ty * 8 + 4];
            unsigned long long A[4] = {a01.x, a01.y, a23.x, a23.y};
            unsigned long long B[JP], S[JP];
            if (TN == 8) {
                ulonglong2 b01 = *(ulonglong2*)&Bs[kk][tx * TN];
                ulonglong2 b23 = *(ulonglong2*)&Bs[kk][tx * TN + 4];
                B[0] = b01.x; B[1] = b01.y; B[2] = b23.x; B[3] = b23.y;
            } else {
                ulonglong2 b01 = *(ulonglong2*)&Bs[kk][tx * TN];
                B[0] = b01.x; B[1] = b01.y;
            }
            #pragma unroll
            for (int jp = 0; jp < JP; jp++) S[jp] = swap64(B[jp]);
            #pragma unroll
            for (int ip = 0; ip < 4; ip++)
                #pragma unroll
                for (int jp = 0; jp < JP; jp++) {
                    fma2(accN[ip][jp], A[ip], B[jp]);
                    fma2(accX[ip][jp], A[ip], S[jp]);
                }
        }
        __syncthreads();
    }

    // Unscramble checkerboard into c[8][TN]
    float c[8][TN];
    #pragma unroll
    for (int ip = 0; ip < 4; ip++)
        #pragma unroll
        for (int jp = 0; jp < JP; jp++) {
            c[2 * ip + 0][2 * jp + 0] = lo32(accN[ip][jp]);
            c[2 * ip + 1][2 * jp + 1] = hi32(accN[ip][jp]);
            c[2 * ip + 0][2 * jp + 1] = lo32(accX[ip][jp]);
            c[2 * ip + 1][2 * jp + 0] = hi32(accX[ip][jp]);
        }

    #pragma unroll
    for (int i = 0; i < 8; i++) {
        int n = row0 + ty * 8 + i;
        if (n >= NN) continue;
        #pragma unroll
        for (int j = 0; j < TN; j += 4) {
            int h = tx * TN + j;
            float4 v;
            v.x = c[i][j + 0] + bias[h + 0];
            v.y = c[i][j + 1] + bias[h + 1];
            v.z = c[i][j + 2] + bias[h + 2];
            v.w = c[i][j + 3] + bias[h + 3];
            if (RELU) {
                v.x = fmaxf(v.x, 0.f); v.y = fmaxf(v.y, 0.f);
                v.z = fmaxf(v.z, 0.f); v.w = fmaxf(v.w, 0.f);
            }
            *(float4*)(out + (size_t)n * BN + h) = v;
        }
    }
}

// ---------------------------------------------------------------------------
// Launch
// ---------------------------------------------------------------------------
extern "C" void kernel_launch(void* const* d_in, const int* in_sizes, int n_in,
                              void* d_out, int out_size) {
    const float* x     = (const float*)d_in[0];
    const void*  ei    = d_in[1];
    const float* ew    = (const float*)d_in[2];
    const void*  et    = d_in[3];
    const float* W1    = (const float*)d_in[4];
    const float* root1 = (const float*)d_in[5];
    const float* bias1 = (const float*)d_in[6];
    const float* W2    = (const float*)d_in[7];
    const float* root2 = (const float*)d_in[8];
    const float* bias2 = (const float*)d_in[9];
    float* out = (float*)d_out;

    void *pT = nullptr, *ph = nullptr;
    cudaGetSymbolAddress(&pT, g_T);
    cudaGetSymbolAddress(&ph, g_h);
    const float* Tp = (const float*)pT;
    float*       hp = (float*)ph;

    k_detect<<<1, 1>>>(ei);
    k_zero_cnt<<<(NN + 255) / 256, 256>>>();
    k_edge_stats<<<1024, 256>>>(ei, ew);
    k_inv<<<(NN + 255) / 256, 256>>>();

    // ---- layer 1 ----
    k_zeroT<<<2048, 256>>>();
    k_scatter<<<(EE * 32 + 255) / 256, 256>>>(x, ei, ew, et);
    k_gemm<128, 8, true><<<(NN + 127) / 128, 256>>>(Tp, W1, x, root1, bias1, hp);

    // ---- layer 2 ----
    k_zeroT<<<2048, 256>>>();
    k_scatter<<<(EE * 32 + 255) / 256, 256>>>(hp, ei, ew, et);
    k_gemm<64, 4, false><<<(NN + 127) / 128, 256>>>(Tp, W2, hp, root2, bias2, out);
}